// round 11
// baseline (speedup 1.0000x reference)
#include <cuda_runtime.h>
#include <cstdint>

#define G 32           // groups
#define CG 2           // channels per group (C=64)
#define MAXB 1024      // max supported batch size for scratch sizing
#define EPSF 1e-5f
#define U 8            // points per chunk (one warp-iteration)
#define GRAIN 64       // points per work-steal grab (8 chunks)
#define NSM 148        // sm count floor (GB300 has 152)
#define BPSM 5         // resident blocks per SM at 256 thr / <=51 regs

// Scratch (device globals; zero-initialized at load). The kernel self-resets
// every mutable global before exit so each graph replay starts clean.
__device__ float  g_s1[MAXB * G];
__device__ float  g_s2[MAXB * G];
__device__ float  g_cnt[MAXB];
__device__ __align__(16) float2 g_mi[MAXB * G];   // (mean, inv) per (b, g)
__device__ unsigned int g_work1  = 0;  // stats steal counter
__device__ unsigned int g_work2  = 0;  // normalize steal counter
__device__ unsigned int g_arrive = 0;  // barrier arrivals
__device__ unsigned int g_release = 0; // barrier release flag
__device__ unsigned int g_depart = 0;  // departure counter (reset owner)

// packed helpers (f32x2 — PTX-only on sm_103a)
__device__ __forceinline__ unsigned long long pack_f32x2(float lo, float hi) {
    unsigned long long r;
    asm("mov.b64 %0, {%1, %2};" : "=l"(r) : "f"(lo), "f"(hi));
    return r;
}
__device__ __forceinline__ void unpack_f32x2(unsigned long long v, float& lo, float& hi) {
    asm("mov.b64 {%0, %1}, %2;" : "=f"(lo), "=f"(hi) : "l"(v));
}
__device__ __forceinline__ void acc_if_eq(unsigned long long& acc, int b, int bb,
                                          unsigned long long vp) {
    asm("{\n\t"
        ".reg .pred p;\n\t"
        "setp.eq.s32 p, %1, %2;\n\t"
        "@p add.rn.f32x2 %0, %0, %3;\n\t"
        "}" : "+l"(acc) : "r"(b), "r"(bb), "l"(vp));
}

// ---------------------------------------------------------------------------
// Fused persistent kernel: stats (work-stealing, ascending) -> device barrier
// + finalize in last-arriving block -> normalize (work-stealing, DESCENDING
// so first reads hit the L2 tail left warm by stats).
// ---------------------------------------------------------------------------
__global__ void __launch_bounds__(256, BPSM) fused_kernel(const float* __restrict__ feat,
                                                          const int* __restrict__ bidx,
                                                          const float* __restrict__ w,
                                                          const float* __restrict__ bias,
                                                          float* __restrict__ out,
                                                          int N, const int* __restrict__ Bp) {
    const int B = *Bp;
    const int lane = threadIdx.x & 31;
    const int ngrains = (N + GRAIN - 1) / GRAIN;

    // ======================= Phase A: stats =======================
    if (B <= 8) {
        unsigned long long acc[8];   // packed (sum, sumsq) per bin
#pragma unroll
        for (int bb = 0; bb < 8; bb++) acc[bb] = 0ULL;
        float cnt = 0.0f;            // lane L accumulates count of bin L (L<8)

        for (;;) {
            int g;
            if (lane == 0) g = (int)atomicAdd(&g_work1, 1u);
            g = __shfl_sync(0xFFFFFFFFu, g, 0);
            if (g >= ngrains) break;
            const int gb   = g * GRAIN;
            const int gend = (gb + GRAIN < N) ? gb + GRAIN : N;

            int base = gb;
            for (; base + (U - 1) < gend; base += U) {
                const int myb = (lane < U) ? __ldg(bidx + base + lane) : 0;
                float2 xb[U];
#pragma unroll
                for (int j = 0; j < U; j++)
                    xb[j] = __ldg(reinterpret_cast<const float2*>(
                                  feat + (size_t)(base + j) * 64) + lane);
#pragma unroll
                for (int j = 0; j < U; j++) {
                    const int b = __shfl_sync(0xFFFFFFFFu, myb, j);
                    const float v  = xb[j].x + xb[j].y;
                    const float v2 = fmaf(xb[j].x, xb[j].x, xb[j].y * xb[j].y);
                    const unsigned long long vp = pack_f32x2(v, v2);
#pragma unroll
                    for (int bb = 0; bb < 8; bb++) acc_if_eq(acc[bb], b, bb, vp);
                    if (lane == b) cnt += 1.0f;
                }
            }
            for (; base < gend; base++) {
                const int b = __ldg(bidx + base);
                const float2 x = __ldg(reinterpret_cast<const float2*>(
                                       feat + (size_t)base * 64) + lane);
                const unsigned long long vp =
                    pack_f32x2(x.x + x.y, fmaf(x.x, x.x, x.y * x.y));
#pragma unroll
                for (int bb = 0; bb < 8; bb++) acc_if_eq(acc[bb], b, bb, vp);
                if (lane == b) cnt += 1.0f;
            }
        }

        // Block-level reduction in shared, then <=520 global atomics per block
        __shared__ float sh1[8 * G];
        __shared__ float sh2[8 * G];
        __shared__ float shc[8];
        for (int i = threadIdx.x; i < 8 * G; i += blockDim.x) { sh1[i] = 0.0f; sh2[i] = 0.0f; }
        if (threadIdx.x < 8) shc[threadIdx.x] = 0.0f;
        __syncthreads();
#pragma unroll
        for (int bb = 0; bb < 8; bb++) {
            float a1, a2;
            unpack_f32x2(acc[bb], a1, a2);
            atomicAdd(&sh1[bb * G + lane], a1);
            atomicAdd(&sh2[bb * G + lane], a2);
        }
        if (lane < 8 && cnt != 0.0f) atomicAdd(&shc[lane], cnt);
        __syncthreads();
        const int i = threadIdx.x;            // exactly 256 = 8*G entries
        if (sh1[i] != 0.0f || sh2[i] != 0.0f) {
            atomicAdd(&g_s1[i], sh1[i]);
            atomicAdd(&g_s2[i], sh2[i]);
        }
        if (i < 8 && shc[i] != 0.0f) atomicAdd(&g_cnt[i], shc[i]);
    } else {
        // Generic fallback (B>8): stealing + per-point global atomics
        for (;;) {
            int g;
            if (lane == 0) g = (int)atomicAdd(&g_work1, 1u);
            g = __shfl_sync(0xFFFFFFFFu, g, 0);
            if (g >= ngrains) break;
            const int gb   = g * GRAIN;
            const int gend = (gb + GRAIN < N) ? gb + GRAIN : N;
            for (int p = gb; p < gend; p++) {
                const int b = __ldg(bidx + p);
                if (b < 0 || b >= MAXB) continue;
                const float2 x = __ldg(reinterpret_cast<const float2*>(
                                       feat + (size_t)p * 64) + lane);
                atomicAdd(&g_s1[b * G + lane], x.x + x.y);
                atomicAdd(&g_s2[b * G + lane], fmaf(x.x, x.x, x.y * x.y));
                if (lane == 0) atomicAdd(&g_cnt[b], 1.0f);
            }
        }
    }

    // ================== device barrier + finalize ==================
    __threadfence();
    __shared__ unsigned int s_ticket;
    if (threadIdx.x == 0) s_ticket = atomicAdd(&g_arrive, 1u);
    __syncthreads();

    if (s_ticket == (unsigned)(gridDim.x - 1)) {
        // Last-arriving block: all other blocks' accumulations are visible.
        int BB = B < 1 ? 1 : (B > MAXB ? MAXB : B);
        for (int i2 = threadIdx.x; i2 < BB * G; i2 += blockDim.x) {
            const int b = i2 >> 5;
            const float c    = fmaxf(g_cnt[b] * (float)CG, 1.0f);
            const float mean = g_s1[i2] / c;
            const float var  = g_s2[i2] / c - mean * mean;
            const float inv  = rsqrtf(var + EPSF);
            g_mi[i2] = make_float2(mean, inv);
            g_s1[i2] = 0.0f;
            g_s2[i2] = 0.0f;
        }
        __syncthreads();
        for (int b = threadIdx.x; b < BB; b += blockDim.x) g_cnt[b] = 0.0f;
        if (threadIdx.x == 0) {
            g_work1 = 0;                       // stats counter: safe, phase A done
            __threadfence();
            atomicExch(&g_release, 1u);        // open the gate
        }
        __syncthreads();
    } else {
        if (threadIdx.x == 0) {
            volatile unsigned int* rel = &g_release;
            while (*rel == 0u) __nanosleep(64);
        }
        __syncthreads();
    }

    // ===================== Phase B: normalize =====================
    // Steal grains in DESCENDING order: first reads hit the high-address tail
    // that stats just left resident in L2.
    {
        const float2 wv = __ldg(reinterpret_cast<const float2*>(w) + lane);
        const float2 bv = __ldg(reinterpret_cast<const float2*>(bias) + lane);

        for (;;) {
            int g;
            if (lane == 0) g = (int)atomicAdd(&g_work2, 1u);
            g = __shfl_sync(0xFFFFFFFFu, g, 0);
            if (g >= ngrains) break;
            g = ngrains - 1 - g;               // reverse sweep
            const int gb   = g * GRAIN;
            const int gend = (gb + GRAIN < N) ? gb + GRAIN : N;

            int base = gb;
            for (; base + (U - 1) < gend; base += U) {
                const int myb = (lane < U) ? __ldg(bidx + base + lane) : 0;
                float2 xb[U];
#pragma unroll
                for (int j = 0; j < U; j++)
                    xb[j] = __ldcs(reinterpret_cast<const float2*>(
                                   feat + (size_t)(base + j) * 64) + lane);
                float2 mi[U];
#pragma unroll
                for (int j = 0; j < U; j++) {
                    const int b = __shfl_sync(0xFFFFFFFFu, myb, j);
                    mi[j] = __ldg(&g_mi[b * G + lane]);
                }
#pragma unroll
                for (int j = 0; j < U; j++) {
                    float2 y;
                    y.x = fmaf(xb[j].x - mi[j].x, mi[j].y * wv.x, bv.x);
                    y.y = fmaf(xb[j].y - mi[j].x, mi[j].y * wv.y, bv.y);
                    __stcs(reinterpret_cast<float2*>(out + (size_t)(base + j) * 64) + lane, y);
                }
            }
            for (; base < gend; base++) {
                const int b = __ldg(bidx + base);
                const float2 mi2 = __ldg(&g_mi[b * G + lane]);
                const float2 x = __ldcs(reinterpret_cast<const float2*>(
                                        feat + (size_t)base * 64) + lane);
                float2 y;
                y.x = fmaf(x.x - mi2.x, mi2.y * wv.x, bv.x);
                y.y = fmaf(x.y - mi2.x, mi2.y * wv.y, bv.y);
                __stcs(reinterpret_cast<float2*>(out + (size_t)base * 64) + lane, y);
            }
        }
    }

    // =================== departure: reset for replay ===================
    __threadfence();
    if (threadIdx.x == 0) {
        const unsigned int d = atomicAdd(&g_depart, 1u);
        if (d == (unsigned)(gridDim.x - 1)) {
            // Every block has fully passed the release gate and finished.
            g_work2  = 0;
            g_arrive = 0;
            g_release = 0;
            g_depart = 0;
            __threadfence();
        }
    }
}

// ---------------------------------------------------------------------------
// kernel_launch
// inputs: 0=features [N*64] f32, 1=weight [64] f32, 2=bias [64] f32,
//         3=batch_idx [N] i32, 4=batch_size [1] i32 (device scalar)
// ---------------------------------------------------------------------------
extern "C" void kernel_launch(void* const* d_in, const int* in_sizes, int n_in,
                              void* d_out, int out_size) {
    const float* feat = (const float*)d_in[0];
    const float* w    = (const float*)d_in[1];
    const float* bias = (const float*)d_in[2];
    const int*   bidx = (const int*)d_in[3];
    const int*   Bp   = (const int*)d_in[4];
    float* out = (float*)d_out;

    const int N = in_sizes[3];           // batch_idx element count == N points

    // All blocks must be co-resident for the device barrier:
    // 148 SMs x 5 blocks/SM guaranteed by __launch_bounds__(256, 5).
    const int blocks = NSM * BPSM;       // 740

    fused_kernel<<<blocks, 256>>>(feat, bidx, w, bias, out, N, Bp);
}

// round 12
// speedup vs baseline: 1.0075x; 1.0075x over previous
#include <cuda_runtime.h>
#include <cstdint>

#define G 32           // groups
#define CG 2           // channels per group (C=64)
#define MAXB 1024      // max supported batch size for scratch sizing
#define EPSF 1e-5f
#define U 8            // points per chunk (one warp-iteration)
#define NSM 148        // sm count floor
#define BPSM 5         // resident blocks per SM
#define STAGE_BYTES (U * 256)   // 2KB: one chunk (8 points x 64 ch x 4B)

// Scratch (device globals: allocation-free per harness rules).
// Zero-initialized at load; the fused finalize (last stats block) self-resets
// everything it consumed, so every graph replay sees zeroed accumulators.
__device__ float  g_s1[MAXB * G];
__device__ float  g_s2[MAXB * G];
__device__ float  g_cnt[MAXB];
__device__ unsigned int g_done = 0;
__device__ __align__(16) float2 g_mi[MAXB * G];   // (mean, inv) per (b, g)

// packed helpers (f32x2 — PTX-only on sm_103a)
__device__ __forceinline__ unsigned long long pack_f32x2(float lo, float hi) {
    unsigned long long r;
    asm("mov.b64 %0, {%1, %2};" : "=l"(r) : "f"(lo), "f"(hi));
    return r;
}
__device__ __forceinline__ void unpack_f32x2(unsigned long long v, float& lo, float& hi) {
    asm("mov.b64 {%0, %1}, %2;" : "=f"(lo), "=f"(hi) : "l"(v));
}
__device__ __forceinline__ void acc_if_eq(unsigned long long& acc, int b, int bb,
                                          unsigned long long vp) {
    asm("{\n\t"
        ".reg .pred p;\n\t"
        "setp.eq.s32 p, %1, %2;\n\t"
        "@p add.rn.f32x2 %0, %0, %3;\n\t"
        "}" : "+l"(acc) : "r"(b), "r"(bb), "l"(vp));
}

// cp.async helpers
__device__ __forceinline__ void cp_async16(uint32_t saddr, const void* gaddr) {
    asm volatile("cp.async.cg.shared.global [%0], [%1], 16;"
                 :: "r"(saddr), "l"(gaddr));
}
__device__ __forceinline__ void cp_commit() {
    asm volatile("cp.async.commit_group;");
}
__device__ __forceinline__ void cp_wait1() {
    asm volatile("cp.async.wait_group 1;");
}
__device__ __forceinline__ void cp_wait0() {
    asm volatile("cp.async.wait_group 0;");
}

// ---------------------------------------------------------------------------
// Kernel 1: stats with cp.async double-buffered staging (+ fused finalize).
// Warp-per-point, lane L owns group L. Each warp streams the NEXT 2KB chunk
// into its private smem buffer (no destination registers -> loads stay in
// flight during binning), while binning the CURRENT chunk from smem.
// ---------------------------------------------------------------------------
__global__ void __launch_bounds__(256, BPSM) stats_kernel(const float* __restrict__ feat,
                                                          const int* __restrict__ bidx,
                                                          int N, const int* __restrict__ Bp) {
    const int B = *Bp;
    const int lane   = threadIdx.x & 31;
    const int wib    = threadIdx.x >> 5;            // warp in block (0..7)
    const int gwarp  = (blockIdx.x * blockDim.x + threadIdx.x) >> 5;
    const int nwarps = (gridDim.x * blockDim.x) >> 5;

    __shared__ __align__(16) char stage_mem[8][2][STAGE_BYTES];
    __shared__ float sh1[8 * G];
    __shared__ float sh2[8 * G];
    __shared__ float shc[8];

    if (B <= 8) {
        unsigned long long acc[8];   // packed (sum, sumsq) per bin
#pragma unroll
        for (int bb = 0; bb < 8; bb++) acc[bb] = 0ULL;
        float cnt = 0.0f;            // lane L accumulates count of bin L (L<8)

        const uint32_t sb0 = (uint32_t)__cvta_generic_to_shared(&stage_mem[wib][0][0]);
        const uint32_t sb1 = (uint32_t)__cvta_generic_to_shared(&stage_mem[wib][1][0]);

        int base = gwarp * U;
        const int stride = nwarps * U;

        bool have = (base + (U - 1) < N);
        int myb = 0;
        if (have) {
            // prologue: stage chunk 0 into buffer 0
            const char* g = reinterpret_cast<const char*>(feat) + (size_t)base * 256 + lane * 16;
            uint32_t s = sb0 + lane * 16;
#pragma unroll
            for (int k = 0; k < 4; k++) cp_async16(s + k * 512, g + k * 512);
            cp_commit();
            myb = (lane < U) ? __ldg(bidx + base + lane) : 0;
        }

        int cur = 0;
        while (have) {
            const int nbase = base + stride;
            const bool haveNext = (nbase + (U - 1) < N);
            int nmyb = 0;
            if (haveNext) {
                const uint32_t sbn = (cur == 0) ? sb1 : sb0;
                const char* g = reinterpret_cast<const char*>(feat) + (size_t)nbase * 256 + lane * 16;
                uint32_t s = sbn + lane * 16;
#pragma unroll
                for (int k = 0; k < 4; k++) cp_async16(s + k * 512, g + k * 512);
                cp_commit();
                nmyb = (lane < U) ? __ldg(bidx + nbase + lane) : 0;
                cp_wait1();            // current chunk's group complete
            } else {
                cp_wait0();
            }
            __syncwarp();              // cross-lane smem visibility

            // bin current chunk from shared (conflict-free LDS.64)
            const char* sbuf = &stage_mem[wib][cur][0];
#pragma unroll
            for (int j = 0; j < U; j++) {
                const int b = __shfl_sync(0xFFFFFFFFu, myb, j);
                const float2 x = reinterpret_cast<const float2*>(sbuf + j * 256)[lane];
                const float v  = x.x + x.y;
                const float v2 = fmaf(x.x, x.x, x.y * x.y);
                const unsigned long long vp = pack_f32x2(v, v2);
#pragma unroll
                for (int bb = 0; bb < 8; bb++) acc_if_eq(acc[bb], b, bb, vp);
                if (lane == b) cnt += 1.0f;
            }

            base = nbase;
            myb  = nmyb;
            cur ^= 1;
            have = haveNext;
        }
        // tail: at most one warp has base < N here (partial final chunk)
        for (; base < N; base++) {
            const int b = __ldg(bidx + base);
            const float2 x = __ldg(reinterpret_cast<const float2*>(
                                   feat + (size_t)base * 64) + lane);
            const unsigned long long vp =
                pack_f32x2(x.x + x.y, fmaf(x.x, x.x, x.y * x.y));
#pragma unroll
            for (int bb = 0; bb < 8; bb++) acc_if_eq(acc[bb], b, bb, vp);
            if (lane == b) cnt += 1.0f;
        }

        // Block-level reduction in shared, then <=520 global atomics per block
        for (int i = threadIdx.x; i < 8 * G; i += blockDim.x) { sh1[i] = 0.0f; sh2[i] = 0.0f; }
        if (threadIdx.x < 8) shc[threadIdx.x] = 0.0f;
        __syncthreads();
#pragma unroll
        for (int bb = 0; bb < 8; bb++) {
            float a1, a2;
            unpack_f32x2(acc[bb], a1, a2);
            atomicAdd(&sh1[bb * G + lane], a1);
            atomicAdd(&sh2[bb * G + lane], a2);
        }
        if (lane < 8 && cnt != 0.0f) atomicAdd(&shc[lane], cnt);
        __syncthreads();
        const int i = threadIdx.x;            // exactly 256 = 8*G entries
        if (sh1[i] != 0.0f || sh2[i] != 0.0f) {
            atomicAdd(&g_s1[i], sh1[i]);
            atomicAdd(&g_s2[i], sh2[i]);
        }
        if (i < 8 && shc[i] != 0.0f) atomicAdd(&g_cnt[i], shc[i]);
    } else {
        // Generic fallback: per-point global atomics (rare path)
        for (int p = gwarp; p < N; p += nwarps) {
            const int b = __ldg(bidx + p);
            if (b < 0 || b >= MAXB) continue;
            const float2 x = __ldg(reinterpret_cast<const float2*>(
                                   feat + (size_t)p * 64) + lane);
            atomicAdd(&g_s1[b * G + lane], x.x + x.y);
            atomicAdd(&g_s2[b * G + lane], fmaf(x.x, x.x, x.y * x.y));
            if (lane == 0) atomicAdd(&g_cnt[b], 1.0f);
        }
    }

    // ---- fused finalize: the last block to finish computes (mean, inv) and
    // resets all accumulators + the ticket for the next graph replay.
    __shared__ unsigned int s_ticket;
    __threadfence();
    if (threadIdx.x == 0) s_ticket = atomicAdd(&g_done, 1u);
    __syncthreads();
    if (s_ticket == (unsigned)(gridDim.x - 1)) {
        __threadfence();
        int BB = B < 1 ? 1 : (B > MAXB ? MAXB : B);
        for (int i2 = threadIdx.x; i2 < BB * G; i2 += blockDim.x) {
            const int b = i2 >> 5;
            const float c    = fmaxf(g_cnt[b] * (float)CG, 1.0f);
            const float mean = g_s1[i2] / c;
            const float var  = g_s2[i2] / c - mean * mean;
            const float inv  = rsqrtf(var + EPSF);
            g_mi[i2] = make_float2(mean, inv);
            g_s1[i2] = 0.0f;
            g_s2[i2] = 0.0f;
        }
        __syncthreads();
        for (int b = threadIdx.x; b < BB; b += blockDim.x) g_cnt[b] = 0.0f;
        if (threadIdx.x == 0) g_done = 0;
    }
}

// ---------------------------------------------------------------------------
// Kernel 2: normalize — R10 best-measured form (3-phase float2, reverse
// sweep for L2 carryover, streaming hints, grid 740).
//   out = (x - mean) * inv * w + bias
// ---------------------------------------------------------------------------
__global__ void __launch_bounds__(256, BPSM) normalize_kernel(const float* __restrict__ feat,
                                                              const int* __restrict__ bidx,
                                                              const float* __restrict__ w,
                                                              const float* __restrict__ bias,
                                                              float* __restrict__ out, int N) {
    const int lane   = threadIdx.x & 31;
    const int gwarp  = (blockIdx.x * blockDim.x + threadIdx.x) >> 5;
    const int nwarps = (gridDim.x * blockDim.x) >> 5;

    const float2 wv = __ldg(reinterpret_cast<const float2*>(w) + lane);
    const float2 bv = __ldg(reinterpret_cast<const float2*>(bias) + lane);

    const int base0  = gwarp * U;
    const int stride = nwarps * U;

    int T = 0;
    if (base0 <= N - U) T = (N - U - base0) / stride + 1;

    // Tail first (at most one warp has a partial final chunk).
    for (int p = base0 + T * stride; p < N; p++) {
        const int b = __ldg(bidx + p);
        const float2 mi2 = __ldg(&g_mi[b * G + lane]);
        const float2 x = __ldcs(reinterpret_cast<const float2*>(
                                feat + (size_t)p * 64) + lane);
        float2 y;
        y.x = fmaf(x.x - mi2.x, mi2.y * wv.x, bv.x);
        y.y = fmaf(x.y - mi2.x, mi2.y * wv.y, bv.y);
        __stcs(reinterpret_cast<float2*>(out + (size_t)p * 64) + lane, y);
    }

    // Main loop: descending chunk order (global back-to-front sweep).
    for (int t = T - 1; t >= 0; t--) {
        const int base = base0 + t * stride;
        const int myb = (lane < U) ? __ldg(bidx + base + lane) : 0;
        float2 xb[U];
#pragma unroll
        for (int j = 0; j < U; j++)
            xb[j] = __ldcs(reinterpret_cast<const float2*>(
                           feat + (size_t)(base + j) * 64) + lane);
        float2 mi[U];
#pragma unroll
        for (int j = 0; j < U; j++) {
            const int b = __shfl_sync(0xFFFFFFFFu, myb, j);
            mi[j] = __ldg(&g_mi[b * G + lane]);
        }
#pragma unroll
        for (int j = 0; j < U; j++) {
            float2 y;
            y.x = fmaf(xb[j].x - mi[j].x, mi[j].y * wv.x, bv.x);
            y.y = fmaf(xb[j].y - mi[j].x, mi[j].y * wv.y, bv.y);
            __stcs(reinterpret_cast<float2*>(out + (size_t)(base + j) * 64) + lane, y);
        }
    }
}

// ---------------------------------------------------------------------------
// kernel_launch
// inputs: 0=features [N*64] f32, 1=weight [64] f32, 2=bias [64] f32,
//         3=batch_idx [N] i32, 4=batch_size [1] i32 (device scalar)
// ---------------------------------------------------------------------------
extern "C" void kernel_launch(void* const* d_in, const int* in_sizes, int n_in,
                              void* d_out, int out_size) {
    const float* feat = (const float*)d_in[0];
    const float* w    = (const float*)d_in[1];
    const float* bias = (const float*)d_in[2];
    const int*   bidx = (const int*)d_in[3];
    const int*   Bp   = (const int*)d_in[4];
    float* out = (float*)d_out;

    const int N = in_sizes[3];           // batch_idx element count == N points

    const int threads = 256;

    // Stats: oversubscribed grid -> tail balancing (best measured).
    int stats_blocks = (N + 31) / 32;
    if (stats_blocks > 1184) stats_blocks = 1184;
    if (stats_blocks < 1) stats_blocks = 1;

    // Normalize: one resident wave (best measured).
    int norm_blocks = NSM * BPSM;        // 740
    int need = (N + 31) / 32;
    if (norm_blocks > need) norm_blocks = need;
    if (norm_blocks < 1) norm_blocks = 1;

    stats_kernel<<<stats_blocks, threads>>>(feat, bidx, N, Bp);
    normalize_kernel<<<norm_blocks, threads>>>(feat, bidx, w, bias, out, N);
}

// round 13
// speedup vs baseline: 1.0100x; 1.0025x over previous
#include <cuda_runtime.h>
#include <cstdint>

#define G 32           // groups
#define CG 2           // channels per group (C=64)
#define MAXB 1024      // max supported batch size for scratch sizing
#define EPSF 1e-5f
#define U 8            // points per warp-iteration
#define NSM 148        // sm count floor
#define BPSM_STATS 6   // stats: 6 blocks/SM (42-reg cap) -> 48 warps/SM
#define BPSM_NORM 5    // normalize: 5 blocks/SM (proven best)

// Scratch (device globals: allocation-free per harness rules).
// Zero-initialized at load; the fused finalize (last stats block) self-resets
// everything it consumed, so every graph replay sees zeroed accumulators.
__device__ float  g_s1[MAXB * G];
__device__ float  g_s2[MAXB * G];
__device__ float  g_cnt[MAXB];
__device__ unsigned int g_done = 0;
__device__ __align__(16) float2 g_mi[MAXB * G];   // (mean, inv) per (b, g)

// packed helpers (f32x2 — PTX-only on sm_103a)
__device__ __forceinline__ unsigned long long pack_f32x2(float lo, float hi) {
    unsigned long long r;
    asm("mov.b64 %0, {%1, %2};" : "=l"(r) : "f"(lo), "f"(hi));
    return r;
}
__device__ __forceinline__ void unpack_f32x2(unsigned long long v, float& lo, float& hi) {
    asm("mov.b64 {%0, %1}, %2;" : "=f"(lo), "=f"(hi) : "l"(v));
}
__device__ __forceinline__ void acc_if_eq(unsigned long long& acc, int b, int bb,
                                          unsigned long long vp) {
    asm("{\n\t"
        ".reg .pred p;\n\t"
        "setp.eq.s32 p, %1, %2;\n\t"
        "@p add.rn.f32x2 %0, %0, %3;\n\t"
        "}" : "+l"(acc) : "r"(b), "r"(bb), "l"(vp));
}

// ---------------------------------------------------------------------------
// Kernel 1: stats (+ fused finalize in the last block to finish).
// R5/R10 form: grid 1184, plain __ldg, MLP=8 front-batched loads, packed
// f32x2 predicated binning. Single change vs R10: 6 blocks/SM occupancy
// (42-reg cap) for +20% resident warps.
// ---------------------------------------------------------------------------
__global__ void __launch_bounds__(256, BPSM_STATS) stats_kernel(const float* __restrict__ feat,
                                                                const int* __restrict__ bidx,
                                                                int N, const int* __restrict__ Bp) {
    const int B = *Bp;
    const int lane   = threadIdx.x & 31;
    const int gwarp  = (blockIdx.x * blockDim.x + threadIdx.x) >> 5;
    const int nwarps = (gridDim.x * blockDim.x) >> 5;

    if (B <= 8) {
        unsigned long long acc[8];   // packed (sum, sumsq) per bin
#pragma unroll
        for (int bb = 0; bb < 8; bb++) acc[bb] = 0ULL;
        float cnt = 0.0f;            // lane L accumulates count of bin L (L<8)

        int base = gwarp * U;
        const int stride = nwarps * U;
        for (; base + (U - 1) < N; base += stride) {
            const int myb = (lane < U) ? __ldg(bidx + base + lane) : 0;
            float2 xb[U];
#pragma unroll
            for (int j = 0; j < U; j++)
                xb[j] = __ldg(reinterpret_cast<const float2*>(
                              feat + (size_t)(base + j) * 64) + lane);
#pragma unroll
            for (int j = 0; j < U; j++) {
                const int b = __shfl_sync(0xFFFFFFFFu, myb, j);
                const float v  = xb[j].x + xb[j].y;
                const float v2 = fmaf(xb[j].x, xb[j].x, xb[j].y * xb[j].y);
                const unsigned long long vp = pack_f32x2(v, v2);
#pragma unroll
                for (int bb = 0; bb < 8; bb++) acc_if_eq(acc[bb], b, bb, vp);
                if (lane == b) cnt += 1.0f;
            }
        }
        for (; base < N; base++) {
            const int b = __ldg(bidx + base);
            const float2 x = __ldg(reinterpret_cast<const float2*>(
                                   feat + (size_t)base * 64) + lane);
            const unsigned long long vp =
                pack_f32x2(x.x + x.y, fmaf(x.x, x.x, x.y * x.y));
#pragma unroll
            for (int bb = 0; bb < 8; bb++) acc_if_eq(acc[bb], b, bb, vp);
            if (lane == b) cnt += 1.0f;
        }

        __shared__ float sh1[8 * G];
        __shared__ float sh2[8 * G];
        __shared__ float shc[8];
        for (int i = threadIdx.x; i < 8 * G; i += blockDim.x) { sh1[i] = 0.0f; sh2[i] = 0.0f; }
        if (threadIdx.x < 8) shc[threadIdx.x] = 0.0f;
        __syncthreads();
#pragma unroll
        for (int bb = 0; bb < 8; bb++) {
            float a1, a2;
            unpack_f32x2(acc[bb], a1, a2);
            atomicAdd(&sh1[bb * G + lane], a1);
            atomicAdd(&sh2[bb * G + lane], a2);
        }
        if (lane < 8 && cnt != 0.0f) atomicAdd(&shc[lane], cnt);
        __syncthreads();
        const int i = threadIdx.x;            // exactly 256 = 8*G entries
        if (sh1[i] != 0.0f || sh2[i] != 0.0f) {
            atomicAdd(&g_s1[i], sh1[i]);
            atomicAdd(&g_s2[i], sh2[i]);
        }
        if (i < 8 && shc[i] != 0.0f) atomicAdd(&g_cnt[i], shc[i]);
    } else {
        // Generic fallback: per-point global atomics (rare path)
        for (int p = gwarp; p < N; p += nwarps) {
            const int b = __ldg(bidx + p);
            if (b < 0 || b >= MAXB) continue;
            const float2 x = __ldg(reinterpret_cast<const float2*>(
                                   feat + (size_t)p * 64) + lane);
            atomicAdd(&g_s1[b * G + lane], x.x + x.y);
            atomicAdd(&g_s2[b * G + lane], fmaf(x.x, x.x, x.y * x.y));
            if (lane == 0) atomicAdd(&g_cnt[b], 1.0f);
        }
    }

    // ---- fused finalize: the last block to finish computes (mean, inv) and
    // resets all accumulators + the ticket for the next graph replay.
    __shared__ unsigned int s_ticket;
    __threadfence();
    if (threadIdx.x == 0) s_ticket = atomicAdd(&g_done, 1u);
    __syncthreads();
    if (s_ticket == (unsigned)(gridDim.x - 1)) {
        __threadfence();
        int BB = B < 1 ? 1 : (B > MAXB ? MAXB : B);
        for (int i2 = threadIdx.x; i2 < BB * G; i2 += blockDim.x) {
            const int b = i2 >> 5;
            const float c    = fmaxf(g_cnt[b] * (float)CG, 1.0f);
            const float mean = g_s1[i2] / c;
            const float var  = g_s2[i2] / c - mean * mean;
            const float inv  = rsqrtf(var + EPSF);
            g_mi[i2] = make_float2(mean, inv);
            g_s1[i2] = 0.0f;
            g_s2[i2] = 0.0f;
        }
        __syncthreads();
        for (int b = threadIdx.x; b < BB; b += blockDim.x) g_cnt[b] = 0.0f;
        if (threadIdx.x == 0) g_done = 0;
    }
}

// ---------------------------------------------------------------------------
// Kernel 2: normalize — R10 best-measured form, byte-identical (3-phase
// float2, reverse sweep for L2 carryover, streaming hints, grid 740).
//   out = (x - mean) * inv * w + bias
// ---------------------------------------------------------------------------
__global__ void __launch_bounds__(256, BPSM_NORM) normalize_kernel(const float* __restrict__ feat,
                                                                   const int* __restrict__ bidx,
                                                                   const float* __restrict__ w,
                                                                   const float* __restrict__ bias,
                                                                   float* __restrict__ out, int N) {
    const int lane   = threadIdx.x & 31;
    const int gwarp  = (blockIdx.x * blockDim.x + threadIdx.x) >> 5;
    const int nwarps = (gridDim.x * blockDim.x) >> 5;

    const float2 wv = __ldg(reinterpret_cast<const float2*>(w) + lane);
    const float2 bv = __ldg(reinterpret_cast<const float2*>(bias) + lane);

    const int base0  = gwarp * U;
    const int stride = nwarps * U;

    int T = 0;
    if (base0 <= N - U) T = (N - U - base0) / stride + 1;

    // Tail first (at most one warp has a partial final chunk).
    for (int p = base0 + T * stride; p < N; p++) {
        const int b = __ldg(bidx + p);
        const float2 mi2 = __ldg(&g_mi[b * G + lane]);
        const float2 x = __ldcs(reinterpret_cast<const float2*>(
                                feat + (size_t)p * 64) + lane);
        float2 y;
        y.x = fmaf(x.x - mi2.x, mi2.y * wv.x, bv.x);
        y.y = fmaf(x.y - mi2.x, mi2.y * wv.y, bv.y);
        __stcs(reinterpret_cast<float2*>(out + (size_t)p * 64) + lane, y);
    }

    // Main loop: descending chunk order (global back-to-front sweep).
    for (int t = T - 1; t >= 0; t--) {
        const int base = base0 + t * stride;
        const int myb = (lane < U) ? __ldg(bidx + base + lane) : 0;
        float2 xb[U];
#pragma unroll
        for (int j = 0; j < U; j++)
            xb[j] = __ldcs(reinterpret_cast<const float2*>(
                           feat + (size_t)(base + j) * 64) + lane);
        float2 mi[U];
#pragma unroll
        for (int j = 0; j < U; j++) {
            const int b = __shfl_sync(0xFFFFFFFFu, myb, j);
            mi[j] = __ldg(&g_mi[b * G + lane]);
        }
#pragma unroll
        for (int j = 0; j < U; j++) {
            float2 y;
            y.x = fmaf(xb[j].x - mi[j].x, mi[j].y * wv.x, bv.x);
            y.y = fmaf(xb[j].y - mi[j].x, mi[j].y * wv.y, bv.y);
            __stcs(reinterpret_cast<float2*>(out + (size_t)(base + j) * 64) + lane, y);
        }
    }
}

// ---------------------------------------------------------------------------
// kernel_launch
// inputs: 0=features [N*64] f32, 1=weight [64] f32, 2=bias [64] f32,
//         3=batch_idx [N] i32, 4=batch_size [1] i32 (device scalar)
// ---------------------------------------------------------------------------
extern "C" void kernel_launch(void* const* d_in, const int* in_sizes, int n_in,
                              void* d_out, int out_size) {
    const float* feat = (const float*)d_in[0];
    const float* w    = (const float*)d_in[1];
    const float* bias = (const float*)d_in[2];
    const int*   bidx = (const int*)d_in[3];
    const int*   Bp   = (const int*)d_in[4];
    float* out = (float*)d_out;

    const int N = in_sizes[3];           // batch_idx element count == N points

    const int threads = 256;

    // Stats: oversubscribed grid -> tail balancing (best measured).
    int stats_blocks = (N + 31) / 32;
    if (stats_blocks > 1184) stats_blocks = 1184;
    if (stats_blocks < 1) stats_blocks = 1;

    // Normalize: one resident wave (best measured).
    int norm_blocks = NSM * BPSM_NORM;   // 740
    int need = (N + 31) / 32;
    if (norm_blocks > need) norm_blocks = need;
    if (norm_blocks < 1) norm_blocks = 1;

    stats_kernel<<<stats_blocks, threads>>>(feat, bidx, N, Bp);
    normalize_kernel<<<norm_blocks, threads>>>(feat, bidx, w, bias, out, N);
}

// round 14
// speedup vs baseline: 1.0297x; 1.0195x over previous
#include <cuda_runtime.h>
#include <cstdint>

#define G 32           // groups
#define CG 2           // channels per group (C=64)
#define MAXB 1024      // max supported batch size for scratch sizing
#define EPSF 1e-5f
#define U 8            // points per warp-iteration
#define NSM 148        // sm count floor
#define BPSM_STATS 6
#define BPSM_NORM 5

// Scratch (device globals: allocation-free per harness rules).
// Zero-initialized at load; the fused finalize (last stats block) self-resets
// everything it consumed, so every graph replay sees zeroed accumulators.
__device__ float  g_s1[MAXB * G];
__device__ float  g_s2[MAXB * G];
__device__ float  g_cnt[MAXB];
__device__ unsigned int g_done = 0;
__device__ __align__(16) float2 g_mi[MAXB * G];   // (mean, inv) per (b, g)

// packed helpers (f32x2 — PTX-only on sm_103a)
__device__ __forceinline__ unsigned long long pack_f32x2(float lo, float hi) {
    unsigned long long r;
    asm("mov.b64 %0, {%1, %2};" : "=l"(r) : "f"(lo), "f"(hi));
    return r;
}
__device__ __forceinline__ void unpack_f32x2(unsigned long long v, float& lo, float& hi) {
    asm("mov.b64 {%0, %1}, %2;" : "=f"(lo), "=f"(hi) : "l"(v));
}
__device__ __forceinline__ unsigned long long add_f32x2(unsigned long long a,
                                                        unsigned long long b) {
    unsigned long long r;
    asm("add.rn.f32x2 %0, %1, %2;" : "=l"(r) : "l"(a), "l"(b));
    return r;
}

// ---------------------------------------------------------------------------
// Kernel 1: stats (+ fused finalize in the last block to finish).
// Warp-per-point, lane L owns group L. Binning goes through per-warp shared
// accumulator bins sh_acc[warp][bin][lane] (packed f32x2): per point only
// LDS.64 + add.f32x2 + STS.64 instead of an 8-way predicated register
// scatter (~9 issues/point vs ~20).
// ---------------------------------------------------------------------------
__global__ void __launch_bounds__(256, BPSM_STATS) stats_kernel(const float* __restrict__ feat,
                                                                const int* __restrict__ bidx,
                                                                int N, const int* __restrict__ Bp) {
    const int B = *Bp;
    const int lane   = threadIdx.x & 31;
    const int wib    = threadIdx.x >> 5;           // warp in block (0..7)
    const int gwarp  = (blockIdx.x * blockDim.x + threadIdx.x) >> 5;
    const int nwarps = (gridDim.x * blockDim.x) >> 5;

    // per-warp bins: [warp][bin][lane], packed (s1,s2) as f32x2 in 8B
    __shared__ __align__(16) unsigned long long sh_acc[8][8][32];
    __shared__ float shc[8];

    if (B <= 8) {
        // zero own warp's slice (warp-private; no block sync needed)
#pragma unroll
        for (int bb = 0; bb < 8; bb++) sh_acc[wib][bb][lane] = 0ULL;
        float cnt = 0.0f;            // lane L accumulates count of bin L (L<8)

        unsigned long long* const mybins = &sh_acc[wib][0][lane];

        int base = gwarp * U;
        const int stride = nwarps * U;
        for (; base + (U - 1) < N; base += stride) {
            // phase 1: front-batched loads (MLP=8)
            const int myb = (lane < U) ? __ldg(bidx + base + lane) : 0;
            float2 xb[U];
#pragma unroll
            for (int j = 0; j < U; j++)
                xb[j] = __ldg(reinterpret_cast<const float2*>(
                              feat + (size_t)(base + j) * 64) + lane);
            // phase 2: bin through shared accumulators
#pragma unroll
            for (int j = 0; j < U; j++) {
                const int b = __shfl_sync(0xFFFFFFFFu, myb, j);
                const float v  = xb[j].x + xb[j].y;
                const float v2 = fmaf(xb[j].x, xb[j].x, xb[j].y * xb[j].y);
                unsigned long long* slot = mybins + b * 32;
                *slot = add_f32x2(*slot, pack_f32x2(v, v2));
                if (lane == b) cnt += 1.0f;
            }
        }
        // tail
        for (; base < N; base++) {
            const int b = __ldg(bidx + base);
            const float2 x = __ldg(reinterpret_cast<const float2*>(
                                   feat + (size_t)base * 64) + lane);
            unsigned long long* slot = mybins + b * 32;
            *slot = add_f32x2(*slot, pack_f32x2(x.x + x.y,
                                                fmaf(x.x, x.x, x.y * x.y)));
            if (lane == b) cnt += 1.0f;
        }

        // block reduction: accumulators already in shared.
        if (threadIdx.x < 8) shc[threadIdx.x] = 0.0f;
        __syncthreads();
        if (lane < 8 && cnt != 0.0f) atomicAdd(&shc[lane], cnt);
        __syncthreads();

        // thread i = bb*32+lane (exactly 256 threads): sum 8 warp slices
        {
            const int bb = threadIdx.x >> 5;   // bin
            const int ln = threadIdx.x & 31;   // lane/group
            float a1 = 0.0f, a2 = 0.0f;
#pragma unroll
            for (int wj = 0; wj < 8; wj++) {
                float p1, p2;
                unpack_f32x2(sh_acc[wj][bb][ln], p1, p2);
                a1 += p1; a2 += p2;
            }
            if (a1 != 0.0f || a2 != 0.0f) {
                atomicAdd(&g_s1[bb * G + ln], a1);
                atomicAdd(&g_s2[bb * G + ln], a2);
            }
        }
        if (threadIdx.x < 8 && shc[threadIdx.x] != 0.0f)
            atomicAdd(&g_cnt[threadIdx.x], shc[threadIdx.x]);
    } else {
        // Generic fallback: per-point global atomics (rare path)
        for (int p = gwarp; p < N; p += nwarps) {
            const int b = __ldg(bidx + p);
            if (b < 0 || b >= MAXB) continue;
            const float2 x = __ldg(reinterpret_cast<const float2*>(
                                   feat + (size_t)p * 64) + lane);
            atomicAdd(&g_s1[b * G + lane], x.x + x.y);
            atomicAdd(&g_s2[b * G + lane], fmaf(x.x, x.x, x.y * x.y));
            if (lane == 0) atomicAdd(&g_cnt[b], 1.0f);
        }
    }

    // ---- fused finalize: the last block to finish computes (mean, inv) and
    // resets all accumulators + the ticket for the next graph replay.
    __shared__ unsigned int s_ticket;
    __threadfence();
    if (threadIdx.x == 0) s_ticket = atomicAdd(&g_done, 1u);
    __syncthreads();
    if (s_ticket == (unsigned)(gridDim.x - 1)) {
        __threadfence();
        int BB = B < 1 ? 1 : (B > MAXB ? MAXB : B);
        for (int i2 = threadIdx.x; i2 < BB * G; i2 += blockDim.x) {
            const int b = i2 >> 5;
            const float c    = fmaxf(g_cnt[b] * (float)CG, 1.0f);
            const float mean = g_s1[i2] / c;
            const float var  = g_s2[i2] / c - mean * mean;
            const float inv  = rsqrtf(var + EPSF);
            g_mi[i2] = make_float2(mean, inv);
            g_s1[i2] = 0.0f;
            g_s2[i2] = 0.0f;
        }
        __syncthreads();
        for (int b = threadIdx.x; b < BB; b += blockDim.x) g_cnt[b] = 0.0f;
        if (threadIdx.x == 0) g_done = 0;
    }
}

// ---------------------------------------------------------------------------
// Kernel 2: normalize — R10 best-measured form, byte-identical (3-phase
// float2, reverse sweep for L2 carryover, streaming hints, grid 740).
//   out = (x - mean) * inv * w + bias
// ---------------------------------------------------------------------------
__global__ void __launch_bounds__(256, BPSM_NORM) normalize_kernel(const float* __restrict__ feat,
                                                                   const int* __restrict__ bidx,
                                                                   const float* __restrict__ w,
                                                                   const float* __restrict__ bias,
                                                                   float* __restrict__ out, int N) {
    const int lane   = threadIdx.x & 31;
    const int gwarp  = (blockIdx.x * blockDim.x + threadIdx.x) >> 5;
    const int nwarps = (gridDim.x * blockDim.x) >> 5;

    const float2 wv = __ldg(reinterpret_cast<const float2*>(w) + lane);
    const float2 bv = __ldg(reinterpret_cast<const float2*>(bias) + lane);

    const int base0  = gwarp * U;
    const int stride = nwarps * U;

    int T = 0;
    if (base0 <= N - U) T = (N - U - base0) / stride + 1;

    // Tail first (at most one warp has a partial final chunk).
    for (int p = base0 + T * stride; p < N; p++) {
        const int b = __ldg(bidx + p);
        const float2 mi2 = __ldg(&g_mi[b * G + lane]);
        const float2 x = __ldcs(reinterpret_cast<const float2*>(
                                feat + (size_t)p * 64) + lane);
        float2 y;
        y.x = fmaf(x.x - mi2.x, mi2.y * wv.x, bv.x);
        y.y = fmaf(x.y - mi2.x, mi2.y * wv.y, bv.y);
        __stcs(reinterpret_cast<float2*>(out + (size_t)p * 64) + lane, y);
    }

    // Main loop: descending chunk order (global back-to-front sweep).
    for (int t = T - 1; t >= 0; t--) {
        const int base = base0 + t * stride;
        const int myb = (lane < U) ? __ldg(bidx + base + lane) : 0;
        float2 xb[U];
#pragma unroll
        for (int j = 0; j < U; j++)
            xb[j] = __ldcs(reinterpret_cast<const float2*>(
                           feat + (size_t)(base + j) * 64) + lane);
        float2 mi[U];
#pragma unroll
        for (int j = 0; j < U; j++) {
            const int b = __shfl_sync(0xFFFFFFFFu, myb, j);
            mi[j] = __ldg(&g_mi[b * G + lane]);
        }
#pragma unroll
        for (int j = 0; j < U; j++) {
            float2 y;
            y.x = fmaf(xb[j].x - mi[j].x, mi[j].y * wv.x, bv.x);
            y.y = fmaf(xb[j].y - mi[j].x, mi[j].y * wv.y, bv.y);
            __stcs(reinterpret_cast<float2*>(out + (size_t)(base + j) * 64) + lane, y);
        }
    }
}

// ---------------------------------------------------------------------------
// kernel_launch
// inputs: 0=features [N*64] f32, 1=weight [64] f32, 2=bias [64] f32,
//         3=batch_idx [N] i32, 4=batch_size [1] i32 (device scalar)
// ---------------------------------------------------------------------------
extern "C" void kernel_launch(void* const* d_in, const int* in_sizes, int n_in,
                              void* d_out, int out_size) {
    const float* feat = (const float*)d_in[0];
    const float* w    = (const float*)d_in[1];
    const float* bias = (const float*)d_in[2];
    const int*   bidx = (const int*)d_in[3];
    const int*   Bp   = (const int*)d_in[4];
    float* out = (float*)d_out;

    const int N = in_sizes[3];           // batch_idx element count == N points

    const int threads = 256;

    // Stats: oversubscribed grid -> tail balancing (best measured).
    int stats_blocks = (N + 31) / 32;
    if (stats_blocks > 1184) stats_blocks = 1184;
    if (stats_blocks < 1) stats_blocks = 1;

    // Normalize: one resident wave (best measured).
    int norm_blocks = NSM * BPSM_NORM;   // 740
    int need = (N + 31) / 32;
    if (norm_blocks > need) norm_blocks = need;
    if (norm_blocks < 1) norm_blocks = 1;

    stats_kernel<<<stats_blocks, threads>>>(feat, bidx, N, Bp);
    normalize_kernel<<<norm_blocks, threads>>>(feat, bidx, w, bias, out, N);
}

// round 15
// speedup vs baseline: 1.0618x; 1.0311x over previous
#include <cuda_runtime.h>
#include <cstdint>

#define G 32           // groups
#define CG 2           // channels per group (C=64)
#define MAXB 1024      // max supported batch size for scratch sizing
#define EPSF 1e-5f
#define US 16          // stats: points per warp-iteration (MLP=16)
#define U 8            // normalize: points per warp-iteration
#define NSM 148        // sm count floor
#define BPSM 5

// Scratch (device globals: allocation-free per harness rules).
// Zero-initialized at load; the fused finalize (last stats block) self-resets
// everything it consumed, so every graph replay sees zeroed accumulators.
__device__ float  g_s1[MAXB * G];
__device__ float  g_s2[MAXB * G];
__device__ float  g_cnt[MAXB];
__device__ unsigned int g_done = 0;
__device__ __align__(16) float2 g_mi[MAXB * G];   // (mean, inv) per (b, g)

// packed helpers (f32x2 — PTX-only on sm_103a)
__device__ __forceinline__ unsigned long long pack_f32x2(float lo, float hi) {
    unsigned long long r;
    asm("mov.b64 %0, {%1, %2};" : "=l"(r) : "f"(lo), "f"(hi));
    return r;
}
__device__ __forceinline__ void unpack_f32x2(unsigned long long v, float& lo, float& hi) {
    asm("mov.b64 {%0, %1}, %2;" : "=f"(lo), "=f"(hi) : "l"(v));
}
__device__ __forceinline__ unsigned long long add_f32x2(unsigned long long a,
                                                        unsigned long long b) {
    unsigned long long r;
    asm("add.rn.f32x2 %0, %1, %2;" : "=l"(r) : "l"(a), "l"(b));
    return r;
}

// ---------------------------------------------------------------------------
// Kernel 1: stats (+ fused finalize in the last block to finish).
// Warp-per-point, lane L owns group L. U=16 front-batched LDG.64 per
// iteration (16 loads in flight per warp — double the previous peak MLP).
// Binning through per-warp shared accumulator bins (packed f32x2), which
// freed the registers that make xb[16] fit at 5 blocks/SM.
// ---------------------------------------------------------------------------
__global__ void __launch_bounds__(256, BPSM) stats_kernel(const float* __restrict__ feat,
                                                          const int* __restrict__ bidx,
                                                          int N, const int* __restrict__ Bp) {
    const int B = *Bp;
    const int lane   = threadIdx.x & 31;
    const int wib    = threadIdx.x >> 5;           // warp in block (0..7)
    const int gwarp  = (blockIdx.x * blockDim.x + threadIdx.x) >> 5;
    const int nwarps = (gridDim.x * blockDim.x) >> 5;

    // per-warp bins: [warp][bin][lane], packed (s1,s2) as f32x2 in 8B
    __shared__ __align__(16) unsigned long long sh_acc[8][8][32];
    __shared__ float shc[8];

    if (B <= 8) {
#pragma unroll
        for (int bb = 0; bb < 8; bb++) sh_acc[wib][bb][lane] = 0ULL;
        float cnt = 0.0f;            // lane L accumulates count of bin L (L<8)

        unsigned long long* const mybins = &sh_acc[wib][0][lane];

        int base = gwarp * US;
        const int stride = nwarps * US;
        for (; base + (US - 1) < N; base += stride) {
            // phase 1: one lane-strided bidx load + 16 front-batched LDG.64
            const int myb = (lane < US) ? __ldg(bidx + base + lane) : 0;
            float2 xb[US];
#pragma unroll
            for (int j = 0; j < US; j++)
                xb[j] = __ldg(reinterpret_cast<const float2*>(
                              feat + (size_t)(base + j) * 64) + lane);
            // phase 2: bin through shared accumulators
#pragma unroll
            for (int j = 0; j < US; j++) {
                const int b = __shfl_sync(0xFFFFFFFFu, myb, j);
                const float v  = xb[j].x + xb[j].y;
                const float v2 = fmaf(xb[j].x, xb[j].x, xb[j].y * xb[j].y);
                unsigned long long* slot = mybins + b * 32;
                *slot = add_f32x2(*slot, pack_f32x2(v, v2));
                if (lane == b) cnt += 1.0f;
            }
        }
        // tail
        for (; base < N; base++) {
            const int b = __ldg(bidx + base);
            const float2 x = __ldg(reinterpret_cast<const float2*>(
                                   feat + (size_t)base * 64) + lane);
            unsigned long long* slot = mybins + b * 32;
            *slot = add_f32x2(*slot, pack_f32x2(x.x + x.y,
                                                fmaf(x.x, x.x, x.y * x.y)));
            if (lane == b) cnt += 1.0f;
        }

        // block reduction: accumulators already in shared.
        if (threadIdx.x < 8) shc[threadIdx.x] = 0.0f;
        __syncthreads();
        if (lane < 8 && cnt != 0.0f) atomicAdd(&shc[lane], cnt);
        __syncthreads();

        // thread i = bb*32+lane (exactly 256 threads): sum 8 warp slices
        {
            const int bb = threadIdx.x >> 5;   // bin
            const int ln = threadIdx.x & 31;   // lane/group
            float a1 = 0.0f, a2 = 0.0f;
#pragma unroll
            for (int wj = 0; wj < 8; wj++) {
                float p1, p2;
                unpack_f32x2(sh_acc[wj][bb][ln], p1, p2);
                a1 += p1; a2 += p2;
            }
            if (a1 != 0.0f || a2 != 0.0f) {
                atomicAdd(&g_s1[bb * G + ln], a1);
                atomicAdd(&g_s2[bb * G + ln], a2);
            }
        }
        if (threadIdx.x < 8 && shc[threadIdx.x] != 0.0f)
            atomicAdd(&g_cnt[threadIdx.x], shc[threadIdx.x]);
    } else {
        // Generic fallback: per-point global atomics (rare path)
        for (int p = gwarp; p < N; p += nwarps) {
            const int b = __ldg(bidx + p);
            if (b < 0 || b >= MAXB) continue;
            const float2 x = __ldg(reinterpret_cast<const float2*>(
                                   feat + (size_t)p * 64) + lane);
            atomicAdd(&g_s1[b * G + lane], x.x + x.y);
            atomicAdd(&g_s2[b * G + lane], fmaf(x.x, x.x, x.y * x.y));
            if (lane == 0) atomicAdd(&g_cnt[b], 1.0f);
        }
    }

    // ---- fused finalize: the last block to finish computes (mean, inv) and
    // resets all accumulators + the ticket for the next graph replay.
    __shared__ unsigned int s_ticket;
    __threadfence();
    if (threadIdx.x == 0) s_ticket = atomicAdd(&g_done, 1u);
    __syncthreads();
    if (s_ticket == (unsigned)(gridDim.x - 1)) {
        __threadfence();
        int BB = B < 1 ? 1 : (B > MAXB ? MAXB : B);
        for (int i2 = threadIdx.x; i2 < BB * G; i2 += blockDim.x) {
            const int b = i2 >> 5;
            const float c    = fmaxf(g_cnt[b] * (float)CG, 1.0f);
            const float mean = g_s1[i2] / c;
            const float var  = g_s2[i2] / c - mean * mean;
            const float inv  = rsqrtf(var + EPSF);
            g_mi[i2] = make_float2(mean, inv);
            g_s1[i2] = 0.0f;
            g_s2[i2] = 0.0f;
        }
        __syncthreads();
        for (int b = threadIdx.x; b < BB; b += blockDim.x) g_cnt[b] = 0.0f;
        if (threadIdx.x == 0) g_done = 0;
    }
}

// ---------------------------------------------------------------------------
// Kernel 2: normalize — R10 best-measured form, byte-identical (3-phase
// float2, reverse sweep for L2 carryover, streaming hints, grid 740).
//   out = (x - mean) * inv * w + bias
// ---------------------------------------------------------------------------
__global__ void __launch_bounds__(256, BPSM) normalize_kernel(const float* __restrict__ feat,
                                                              const int* __restrict__ bidx,
                                                              const float* __restrict__ w,
                                                              const float* __restrict__ bias,
                                                              float* __restrict__ out, int N) {
    const int lane   = threadIdx.x & 31;
    const int gwarp  = (blockIdx.x * blockDim.x + threadIdx.x) >> 5;
    const int nwarps = (gridDim.x * blockDim.x) >> 5;

    const float2 wv = __ldg(reinterpret_cast<const float2*>(w) + lane);
    const float2 bv = __ldg(reinterpret_cast<const float2*>(bias) + lane);

    const int base0  = gwarp * U;
    const int stride = nwarps * U;

    int T = 0;
    if (base0 <= N - U) T = (N - U - base0) / stride + 1;

    // Tail first (at most one warp has a partial final chunk).
    for (int p = base0 + T * stride; p < N; p++) {
        const int b = __ldg(bidx + p);
        const float2 mi2 = __ldg(&g_mi[b * G + lane]);
        const float2 x = __ldcs(reinterpret_cast<const float2*>(
                                feat + (size_t)p * 64) + lane);
        float2 y;
        y.x = fmaf(x.x - mi2.x, mi2.y * wv.x, bv.x);
        y.y = fmaf(x.y - mi2.x, mi2.y * wv.y, bv.y);
        __stcs(reinterpret_cast<float2*>(out + (size_t)p * 64) + lane, y);
    }

    // Main loop: descending chunk order (global back-to-front sweep).
    for (int t = T - 1; t >= 0; t--) {
        const int base = base0 + t * stride;
        const int myb = (lane < U) ? __ldg(bidx + base + lane) : 0;
        float2 xb[U];
#pragma unroll
        for (int j = 0; j < U; j++)
            xb[j] = __ldcs(reinterpret_cast<const float2*>(
                           feat + (size_t)(base + j) * 64) + lane);
        float2 mi[U];
#pragma unroll
        for (int j = 0; j < U; j++) {
            const int b = __shfl_sync(0xFFFFFFFFu, myb, j);
            mi[j] = __ldg(&g_mi[b * G + lane]);
        }
#pragma unroll
        for (int j = 0; j < U; j++) {
            float2 y;
            y.x = fmaf(xb[j].x - mi[j].x, mi[j].y * wv.x, bv.x);
            y.y = fmaf(xb[j].y - mi[j].x, mi[j].y * wv.y, bv.y);
            __stcs(reinterpret_cast<float2*>(out + (size_t)(base + j) * 64) + lane, y);
        }
    }
}

// ---------------------------------------------------------------------------
// kernel_launch
// inputs: 0=features [N*64] f32, 1=weight [64] f32, 2=bias [64] f32,
//         3=batch_idx [N] i32, 4=batch_size [1] i32 (device scalar)
// ---------------------------------------------------------------------------
extern "C" void kernel_launch(void* const* d_in, const int* in_sizes, int n_in,
                              void* d_out, int out_size) {
    const float* feat = (const float*)d_in[0];
    const float* w    = (const float*)d_in[1];
    const float* bias = (const float*)d_in[2];
    const int*   bidx = (const int*)d_in[3];
    const int*   Bp   = (const int*)d_in[4];
    float* out = (float*)d_out;

    const int N = in_sizes[3];           // batch_idx element count == N points

    const int threads = 256;

    // Stats: oversubscribed grid -> tail balancing (best measured).
    int stats_blocks = (N + 31) / 32;
    if (stats_blocks > 1184) stats_blocks = 1184;
    if (stats_blocks < 1) stats_blocks = 1;

    // Normalize: one resident wave (best measured).
    int norm_blocks = NSM * BPSM;        // 740
    int need = (N + 31) / 32;
    if (norm_blocks > need) norm_blocks = need;
    if (norm_blocks < 1) norm_blocks = 1;

    stats_kernel<<<stats_blocks, threads>>>(feat, bidx, N, Bp);
    normalize_kernel<<<norm_blocks, threads>>>(feat, bidx, w, bias, out, N);
}